// round 6
// baseline (speedup 1.0000x reference)
#include <cuda_runtime.h>

// out[i] = gen_map[x_gen[i]] + c * x_max_clock_speed[i] + d * x_max_tdp[i]
// N = 8388608 (n4 = 2097152, divisible by BLOCK*VPT -> no bounds checks on fast path).
// Minimal traffic: 16 B/elem. Bottleneck: mixed R/W DRAM stream (~5.5 TB/s observed).

#define BLOCK 256
#define VPT 2  // float4 groups per thread

// Fast path: NO bounds checks (grid exactly covers n4).
__global__ void __launch_bounds__(BLOCK) fused_gather_axpy_fast(
    const int4* __restrict__ x_gen4,
    const float4* __restrict__ cs4,
    const float4* __restrict__ tdp4,
    const float* __restrict__ gen_map,
    const float* __restrict__ c_p,
    const float* __restrict__ d_p,
    float4* __restrict__ out4)
{
    __shared__ float s_map[1024];

    // Cooperative load of gen_map: 256 threads x float4
    ((float4*)s_map)[threadIdx.x] = __ldg(&((const float4*)gen_map)[threadIdx.x]);

    const float c = __ldg(c_p);
    const float d = __ldg(d_p);

    const int base = blockIdx.x * (BLOCK * VPT) + threadIdx.x;

    // Front-batch all 6 streaming loads unconditionally (MLP = 6).
    int4   g0 = __ldcg(&x_gen4[base]);
    int4   g1 = __ldcg(&x_gen4[base + BLOCK]);
    float4 s0 = __ldcg(&cs4[base]);
    float4 s1 = __ldcg(&cs4[base + BLOCK]);
    float4 t0 = __ldcg(&tdp4[base]);
    float4 t1 = __ldcg(&tdp4[base + BLOCK]);

    __syncthreads();

    float4 o0;
    o0.x = s_map[g0.x] + c * s0.x + d * t0.x;
    o0.y = s_map[g0.y] + c * s0.y + d * t0.y;
    o0.z = s_map[g0.z] + c * s0.z + d * t0.z;
    o0.w = s_map[g0.w] + c * s0.w + d * t0.w;
    __stcs(&out4[base], o0);

    float4 o1;
    o1.x = s_map[g1.x] + c * s1.x + d * t1.x;
    o1.y = s_map[g1.y] + c * s1.y + d * t1.y;
    o1.z = s_map[g1.z] + c * s1.z + d * t1.z;
    o1.w = s_map[g1.w] + c * s1.w + d * t1.w;
    __stcs(&out4[base + BLOCK], o1);
}

// Generic fallback (any N), element-granular.
__global__ void fused_gather_axpy_generic(
    const int* __restrict__ x_gen,
    const float* __restrict__ cs,
    const float* __restrict__ tdp,
    const float* __restrict__ gen_map,
    const float* __restrict__ c_p,
    const float* __restrict__ d_p,
    float* __restrict__ out,
    int start, int n)
{
    int i = start + blockIdx.x * blockDim.x + threadIdx.x;
    if (i >= n) return;
    float c = __ldg(c_p);
    float d = __ldg(d_p);
    out[i] = __ldg(&gen_map[x_gen[i]]) + c * cs[i] + d * tdp[i];
}

extern "C" void kernel_launch(void* const* d_in, const int* in_sizes, int n_in,
                              void* d_out, int out_size)
{
    const int*   x_gen   = (const int*)d_in[0];
    // d_in[1] = x_ix (unused)
    const float* cs      = (const float*)d_in[2];
    const float* tdp     = (const float*)d_in[3];
    const float* gen_map = (const float*)d_in[4];
    // d_in[5] = b (unused)
    const float* c_p     = (const float*)d_in[6];
    const float* d_p     = (const float*)d_in[7];
    float* out = (float*)d_out;

    const int n  = in_sizes[0];
    const int n4 = n / 4;
    const int elems_per_block = BLOCK * VPT;

    if ((n % 4 == 0) && (n4 % elems_per_block == 0)) {
        // Exact-cover fast path (holds for N = 8388608).
        fused_gather_axpy_fast<<<n4 / elems_per_block, BLOCK>>>(
            (const int4*)x_gen, (const float4*)cs, (const float4*)tdp,
            gen_map, c_p, d_p, (float4*)out);
    } else {
        fused_gather_axpy_generic<<<(n + 255) / 256, 256>>>(
            x_gen, cs, tdp, gen_map, c_p, d_p, out, 0, n);
    }
}